// round 5
// baseline (speedup 1.0000x reference)
#include <cuda_runtime.h>
#include <cuda_bf16.h>
#include <cstdint>

#define MAX_ATOMS 40000
#define MAX_EDGES 640000
#define NFM 128

// ---------------------------------------------------------------------------
// Scratch
// ---------------------------------------------------------------------------
__device__ float    g_f[(size_t)MAX_ATOMS * NFM];     // f = x @ W_in
__device__ int      g_rowstart[MAX_ATOMS + 1];        // CSR offsets
// Pre-packed B fragments in mma.m16n8k16 register order.
// [matrix: 0=Win 1=Wout][term: 0=hi 1=lo][ ((t*8+k)*32+lane)*2 + reg ]
__device__ uint32_t g_Bfrag[2][2][8192];

// ---------------------------------------------------------------------------
__device__ __forceinline__ void split_pair(float v0, float v1,
                                           uint32_t& hp, uint32_t& lp) {
    __nv_bfloat16 h0 = __float2bfloat16(v0);
    __nv_bfloat16 h1 = __float2bfloat16(v1);
    __nv_bfloat16 l0 = __float2bfloat16(v0 - __bfloat162float(h0));
    __nv_bfloat16 l1 = __float2bfloat16(v1 - __bfloat162float(h1));
    hp = (uint32_t)__bfloat16_as_ushort(h0) | ((uint32_t)__bfloat16_as_ushort(h1) << 16);
    lp = (uint32_t)__bfloat16_as_ushort(l0) | ((uint32_t)__bfloat16_as_ushort(l1) << 16);
}

__device__ __forceinline__ void mma16816(float* c, const uint32_t* a,
                                         uint32_t b0, uint32_t b1) {
    asm volatile(
        "mma.sync.aligned.m16n8k16.row.col.f32.bf16.bf16.f32 "
        "{%0,%1,%2,%3}, {%4,%5,%6,%7}, {%8,%9}, {%0,%1,%2,%3};"
        : "+f"(c[0]), "+f"(c[1]), "+f"(c[2]), "+f"(c[3])
        : "r"(a[0]), "r"(a[1]), "r"(a[2]), "r"(a[3]), "r"(b0), "r"(b1));
}

#define A_STRIDE 136   // bf16 elems per row (bank-conflict-free)

// ---------------------------------------------------------------------------
// GEMM compute phase from staged split A tile in smem (64x128 tile, 8 warps,
// warp tile 32x32). Shared by gemm_mma_kernel and the fused conv kernel.
// ---------------------------------------------------------------------------
__device__ __forceinline__ void gemm_tile_compute(
    const __nv_bfloat16* Ah, const __nv_bfloat16* Al,
    const uint32_t* __restrict__ Bh, const uint32_t* __restrict__ Bl,
    const float* __restrict__ bias, float* __restrict__ C, int M, int m0,
    int tid)
{
    const int wid  = tid >> 5;
    const int lane = tid & 31;
    const int wm   = wid & 1;                 // M slice (32 rows)
    const int wn   = wid >> 1;                // N slice (32 cols)
    const int g    = lane >> 2;               // 0..7
    const int tg   = lane & 3;                // 0..3

    float acc[2][4][4];
#pragma unroll
    for (int mf = 0; mf < 2; mf++)
#pragma unroll
        for (int t4 = 0; t4 < 4; t4++)
#pragma unroll
            for (int i = 0; i < 4; i++) acc[mf][t4][i] = 0.f;

#pragma unroll
    for (int k = 0; k < 8; k++) {
        uint32_t ah[2][4], al[2][4];
        const int cb = k * 16 + tg * 2;
#pragma unroll
        for (int mf = 0; mf < 2; mf++) {
            int r = wm * 32 + mf * 16 + g;
            ah[mf][0] = *reinterpret_cast<const uint32_t*>(&Ah[r * A_STRIDE + cb]);
            ah[mf][1] = *reinterpret_cast<const uint32_t*>(&Ah[(r + 8) * A_STRIDE + cb]);
            ah[mf][2] = *reinterpret_cast<const uint32_t*>(&Ah[r * A_STRIDE + cb + 8]);
            ah[mf][3] = *reinterpret_cast<const uint32_t*>(&Ah[(r + 8) * A_STRIDE + cb + 8]);
            al[mf][0] = *reinterpret_cast<const uint32_t*>(&Al[r * A_STRIDE + cb]);
            al[mf][1] = *reinterpret_cast<const uint32_t*>(&Al[(r + 8) * A_STRIDE + cb]);
            al[mf][2] = *reinterpret_cast<const uint32_t*>(&Al[r * A_STRIDE + cb + 8]);
            al[mf][3] = *reinterpret_cast<const uint32_t*>(&Al[(r + 8) * A_STRIDE + cb + 8]);
        }
#pragma unroll
        for (int t4 = 0; t4 < 4; t4++) {
            int fidx = (((wn * 4 + t4) * 8 + k) * 32 + lane) * 2;
            uint32_t bh0 = __ldg(&Bh[fidx]);
            uint32_t bh1 = __ldg(&Bh[fidx + 1]);
            uint32_t bl0 = __ldg(&Bl[fidx]);
            uint32_t bl1 = __ldg(&Bl[fidx + 1]);
#pragma unroll
            for (int mf = 0; mf < 2; mf++) {
                mma16816(acc[mf][t4], ah[mf], bh0, bh1);   // Ah*Bh
                mma16816(acc[mf][t4], ah[mf], bl0, bl1);   // Ah*Bl
                mma16816(acc[mf][t4], al[mf], bh0, bh1);   // Al*Bh
            }
        }
    }

#pragma unroll
    for (int t4 = 0; t4 < 4; t4++) {
        int col = wn * 32 + t4 * 8 + tg * 2;
        float b0 = bias ? __ldg(&bias[col])     : 0.f;
        float b1 = bias ? __ldg(&bias[col + 1]) : 0.f;
#pragma unroll
        for (int mf = 0; mf < 2; mf++) {
            int row = m0 + wm * 32 + mf * 16 + g;
            if (row < M) {
                float2 o0 = make_float2(acc[mf][t4][0] + b0, acc[mf][t4][1] + b1);
                *reinterpret_cast<float2*>(&C[(size_t)row * 128 + col]) = o0;
            }
            if (row + 8 < M) {
                float2 o1 = make_float2(acc[mf][t4][2] + b0, acc[mf][t4][3] + b1);
                *reinterpret_cast<float2*>(&C[(size_t)(row + 8) * 128 + col]) = o1;
            }
        }
    }
}

// ---------------------------------------------------------------------------
// Prep: pack weights into B-fragment order, split hi/lo. W is [K,N] row-major.
// ---------------------------------------------------------------------------
__global__ void prep_weights_kernel(const float* __restrict__ W_in,
                                    const float* __restrict__ W_out)
{
    int id = blockIdx.x * blockDim.x + threadIdx.x;   // 0..32767
    int reg  = id & 1;
    int lane = (id >> 1) & 31;
    int k    = (id >> 6) & 7;
    int t    = (id >> 9) & 15;
    int term = (id >> 13) & 1;
    int mat  = (id >> 14) & 1;

    const float* W = mat ? W_out : W_in;
    int kr = k * 16 + (lane & 3) * 2 + reg * 8;
    int n  = t * 8 + (lane >> 2);
    float v0 = W[(size_t)kr * 128 + n];
    float v1 = W[(size_t)(kr + 1) * 128 + n];
    uint32_t hp, lp;
    split_pair(v0, v1, hp, lp);
    g_Bfrag[mat][term][(((t * 8 + k) * 32) + lane) * 2 + reg] = term ? lp : hp;
}

// ---------------------------------------------------------------------------
// GEMM1: C[M,128] = A[M,128] @ W[128,128]. A staged from global.
// ---------------------------------------------------------------------------
__global__ __launch_bounds__(256, 2)
void gemm_mma_kernel(const float* __restrict__ A,
                     const uint32_t* __restrict__ Bh,
                     const uint32_t* __restrict__ Bl,
                     const float* __restrict__ bias,
                     float* __restrict__ C, int M)
{
    extern __shared__ __nv_bfloat16 sA[];     // [2][64][A_STRIDE]
    __nv_bfloat16* Ah = sA;
    __nv_bfloat16* Al = sA + 64 * A_STRIDE;

    const int tid = threadIdx.x;
    const int m0  = blockIdx.x * 64;

#pragma unroll
    for (int it = 0; it < 16; it++) {
        int p  = tid + it * 256;
        int m  = p >> 6;
        int kp = (p & 63) << 1;
        float2 v = make_float2(0.f, 0.f);
        if (m0 + m < M)
            v = *reinterpret_cast<const float2*>(&A[(size_t)(m0 + m) * 128 + kp]);
        uint32_t hp, lp;
        split_pair(v.x, v.y, hp, lp);
        *reinterpret_cast<uint32_t*>(&Ah[m * A_STRIDE + kp]) = hp;
        *reinterpret_cast<uint32_t*>(&Al[m * A_STRIDE + kp]) = lp;
    }
    __syncthreads();

    gemm_tile_compute(Ah, Al, Bh, Bl, bias, C, M, m0, tid);
}

// ---------------------------------------------------------------------------
// CSR offsets from sorted seg_i
// ---------------------------------------------------------------------------
__global__ void offsets_kernel(const int* __restrict__ seg_i, int num_edges, int num_atoms)
{
    int a = blockIdx.x * blockDim.x + threadIdx.x;
    if (a > num_atoms) return;
    int lo = 0, hi = num_edges;
    while (lo < hi) {
        int mid = (lo + hi) >> 1;
        if (seg_i[mid] < a) lo = mid + 1; else hi = mid;
    }
    g_rowstart[a] = lo;
}

// ---------------------------------------------------------------------------
// Fused conv + GEMM2: block owns 64 atoms (one GEMM tile). 8 warps x 8 atoms.
// Each warp streams its atoms' contiguous edge range, accumulates in regs,
// flushes each finished atom row into the split-bf16 A tile in smem, then the
// block runs the 64x128 mma tile and writes d_out directly.
// ---------------------------------------------------------------------------
__global__ __launch_bounds__(256, 2)
void conv_gemm_kernel(const float* __restrict__ w_ij,
                      const int* __restrict__ idx_j,
                      const uint32_t* __restrict__ Bh,
                      const uint32_t* __restrict__ Bl,
                      const float* __restrict__ bias,
                      float* __restrict__ C, int M)
{
    extern __shared__ __nv_bfloat16 sA[];     // [2][64][A_STRIDE]
    __nv_bfloat16* Ah = sA;
    __nv_bfloat16* Al = sA + 64 * A_STRIDE;

    const int tid  = threadIdx.x;
    const int wid  = tid >> 5;
    const int lane = tid & 31;
    const int m0   = blockIdx.x * 64;
    const int a0   = m0 + wid * 8;
    const int c    = lane * 4;

#pragma unroll 1
    for (int slot = 0; slot < 8; slot++) {
        const int a = a0 + slot;
        const int r = wid * 8 + slot;         // local tile row
        float4 acc = make_float4(0.f, 0.f, 0.f, 0.f);

        if (a < M) {
            int k = g_rowstart[a];
            const int e = g_rowstart[a + 1];

            int j0 = 0, j1 = 0, j2 = 0, j3 = 0;
            if (k + 3 < e) {
                j0 = __ldg(&idx_j[k]);     j1 = __ldg(&idx_j[k + 1]);
                j2 = __ldg(&idx_j[k + 2]); j3 = __ldg(&idx_j[k + 3]);
            }
            while (k + 3 < e) {
                // prefetch next group's indices before this group's FMAs
                int t0 = 0, t1 = 0, t2 = 0, t3 = 0;
                if (k + 7 < e) {
                    t0 = __ldg(&idx_j[k + 4]); t1 = __ldg(&idx_j[k + 5]);
                    t2 = __ldg(&idx_j[k + 6]); t3 = __ldg(&idx_j[k + 7]);
                }
                float4 w0 = __ldcs(reinterpret_cast<const float4*>(&w_ij[(size_t)k * 128 + c]));
                float4 w1 = __ldcs(reinterpret_cast<const float4*>(&w_ij[(size_t)(k + 1) * 128 + c]));
                float4 w2 = __ldcs(reinterpret_cast<const float4*>(&w_ij[(size_t)(k + 2) * 128 + c]));
                float4 w3 = __ldcs(reinterpret_cast<const float4*>(&w_ij[(size_t)(k + 3) * 128 + c]));
                float4 f0 = __ldg(reinterpret_cast<const float4*>(&g_f[(size_t)j0 * 128 + c]));
                float4 f1 = __ldg(reinterpret_cast<const float4*>(&g_f[(size_t)j1 * 128 + c]));
                float4 f2 = __ldg(reinterpret_cast<const float4*>(&g_f[(size_t)j2 * 128 + c]));
                float4 f3 = __ldg(reinterpret_cast<const float4*>(&g_f[(size_t)j3 * 128 + c]));
                acc.x = fmaf(w0.x, f0.x, acc.x); acc.y = fmaf(w0.y, f0.y, acc.y);
                acc.z = fmaf(w0.z, f0.z, acc.z); acc.w = fmaf(w0.w, f0.w, acc.w);
                acc.x = fmaf(w1.x, f1.x, acc.x); acc.y = fmaf(w1.y, f1.y, acc.y);
                acc.z = fmaf(w1.z, f1.z, acc.z); acc.w = fmaf(w1.w, f1.w, acc.w);
                acc.x = fmaf(w2.x, f2.x, acc.x); acc.y = fmaf(w2.y, f2.y, acc.y);
                acc.z = fmaf(w2.z, f2.z, acc.z); acc.w = fmaf(w2.w, f2.w, acc.w);
                acc.x = fmaf(w3.x, f3.x, acc.x); acc.y = fmaf(w3.y, f3.y, acc.y);
                acc.z = fmaf(w3.z, f3.z, acc.z); acc.w = fmaf(w3.w, f3.w, acc.w);
                j0 = t0; j1 = t1; j2 = t2; j3 = t3;
                k += 4;
            }
            for (; k < e; k++) {
                int j = __ldg(&idx_j[k]);
                float4 w0 = __ldcs(reinterpret_cast<const float4*>(&w_ij[(size_t)k * 128 + c]));
                float4 f0 = __ldg(reinterpret_cast<const float4*>(&g_f[(size_t)j * 128 + c]));
                acc.x = fmaf(w0.x, f0.x, acc.x); acc.y = fmaf(w0.y, f0.y, acc.y);
                acc.z = fmaf(w0.z, f0.z, acc.z); acc.w = fmaf(w0.w, f0.w, acc.w);
            }
        }

        // flush row r as split bf16 directly into the GEMM A tile
        uint32_t hp0, lp0, hp1, lp1;
        split_pair(acc.x, acc.y, hp0, lp0);
        split_pair(acc.z, acc.w, hp1, lp1);
        *reinterpret_cast<uint2*>(&Ah[r * A_STRIDE + c]) = make_uint2(hp0, hp1);
        *reinterpret_cast<uint2*>(&Al[r * A_STRIDE + c]) = make_uint2(lp0, lp1);
    }

    __syncthreads();

    gemm_tile_compute(Ah, Al, Bh, Bl, bias, C, M, m0, tid);
}

// ---------------------------------------------------------------------------
extern "C" void kernel_launch(void* const* d_in, const int* in_sizes, int n_in,
                              void* d_out, int out_size)
{
    const float* x    = (const float*)d_in[0];
    const float* wij  = (const float*)d_in[1];
    const int*   seg  = (const int*)d_in[2];
    const int*   idxj = (const int*)d_in[3];
    int base = 4;
    if (n_in >= 8 && in_sizes[4] == 1) base = 5;   // skip scalar seg_i_sum
    const float* Win  = (const float*)d_in[base];
    const float* Wout = (const float*)d_in[base + 1];
    const float* bout = (const float*)d_in[base + 2];

    int num_edges = in_sizes[2];
    int num_atoms = out_size / NFM;
    if (num_atoms > MAX_ATOMS) num_atoms = MAX_ATOMS;
    if (num_edges > MAX_EDGES) num_edges = MAX_EDGES;

    float*    f_ptr = nullptr;
    uint32_t* bfrag = nullptr;
    cudaGetSymbolAddress((void**)&f_ptr, g_f);
    cudaGetSymbolAddress((void**)&bfrag, g_Bfrag);

    const int SMEM_A = 2 * 64 * A_STRIDE * (int)sizeof(__nv_bfloat16);  // 34816
    cudaFuncSetAttribute(gemm_mma_kernel,
                         cudaFuncAttributeMaxDynamicSharedMemorySize, SMEM_A);
    cudaFuncSetAttribute(conv_gemm_kernel,
                         cudaFuncAttributeMaxDynamicSharedMemorySize, SMEM_A);

    int gblocks = (num_atoms + 63) / 64;

    // 0) pack weights into mma B fragments (hi/lo)
    prep_weights_kernel<<<128, 256>>>(Win, Wout);

    // 1) CSR offsets (independent of GEMM1)
    offsets_kernel<<<(num_atoms + 1 + 255) / 256, 256>>>(seg, num_edges, num_atoms);

    // 2) f = x @ W_in
    gemm_mma_kernel<<<gblocks, 256, SMEM_A>>>(
        x, bfrag + 0 * 8192, bfrag + 1 * 8192, nullptr, f_ptr, num_atoms);

    // 3) fused: conv = segment_sum(w_ij * f[idx_j]);  out = conv @ W_out + b
    conv_gemm_kernel<<<gblocks, 256, SMEM_A>>>(
        wij, idxj, bfrag + 2 * 8192, bfrag + 3 * 8192, bout, (float*)d_out, num_atoms);
}

// round 6
// speedup vs baseline: 1.0601x; 1.0601x over previous
#include <cuda_runtime.h>
#include <cuda_bf16.h>
#include <cstdint>

#define MAX_ATOMS 40000
#define MAX_EDGES 640000
#define NFM 128

// ---------------------------------------------------------------------------
// Scratch
// ---------------------------------------------------------------------------
__device__ float    g_f[(size_t)MAX_ATOMS * NFM];     // f = x @ W_in
__device__ float    g_conv[(size_t)MAX_ATOMS * NFM];  // segment-summed conv
__device__ int      g_rowstart[MAX_ATOMS + 1];        // CSR offsets
// Pre-packed B fragments in mma.m16n8k16 register order.
// [matrix: 0=Win 1=Wout][term: 0=hi 1=lo][ ((t*8+k)*32+lane)*2 + reg ]
__device__ uint32_t g_Bfrag[2][2][8192];

// ---------------------------------------------------------------------------
__device__ __forceinline__ void split_pair(float v0, float v1,
                                           uint32_t& hp, uint32_t& lp) {
    __nv_bfloat16 h0 = __float2bfloat16(v0);
    __nv_bfloat16 h1 = __float2bfloat16(v1);
    __nv_bfloat16 l0 = __float2bfloat16(v0 - __bfloat162float(h0));
    __nv_bfloat16 l1 = __float2bfloat16(v1 - __bfloat162float(h1));
    hp = (uint32_t)__bfloat16_as_ushort(h0) | ((uint32_t)__bfloat16_as_ushort(h1) << 16);
    lp = (uint32_t)__bfloat16_as_ushort(l0) | ((uint32_t)__bfloat16_as_ushort(l1) << 16);
}

__device__ __forceinline__ void mma16816(float* c, const uint32_t* a,
                                         uint32_t b0, uint32_t b1) {
    asm volatile(
        "mma.sync.aligned.m16n8k16.row.col.f32.bf16.bf16.f32 "
        "{%0,%1,%2,%3}, {%4,%5,%6,%7}, {%8,%9}, {%0,%1,%2,%3};"
        : "+f"(c[0]), "+f"(c[1]), "+f"(c[2]), "+f"(c[3])
        : "r"(a[0]), "r"(a[1]), "r"(a[2]), "r"(a[3]), "r"(b0), "r"(b1));
}

// ---------------------------------------------------------------------------
// Prep: pack weights into B-fragment order, split hi/lo. W is [K,N] row-major.
// ---------------------------------------------------------------------------
__global__ void prep_weights_kernel(const float* __restrict__ W_in,
                                    const float* __restrict__ W_out)
{
    int id = blockIdx.x * blockDim.x + threadIdx.x;   // 0..32767
    int reg  = id & 1;
    int lane = (id >> 1) & 31;
    int k    = (id >> 6) & 7;
    int t    = (id >> 9) & 15;
    int term = (id >> 13) & 1;
    int mat  = (id >> 14) & 1;

    const float* W = mat ? W_out : W_in;
    int kr = k * 16 + (lane & 3) * 2 + reg * 8;
    int n  = t * 8 + (lane >> 2);
    float v0 = W[(size_t)kr * 128 + n];
    float v1 = W[(size_t)(kr + 1) * 128 + n];
    uint32_t hp, lp;
    split_pair(v0, v1, hp, lp);
    g_Bfrag[mat][term][(((t * 8 + k) * 32) + lane) * 2 + reg] = term ? lp : hp;
}

// ---------------------------------------------------------------------------
// GEMM via mma.sync: C[M,128] = A[M,128] @ W[128,128] (+bias).
// Split bf16 3-term. CTA: 64x128 tile, 8 warps (warp tile 32x32), 2 CTAs/SM.
// ---------------------------------------------------------------------------
#define A_STRIDE 136   // bf16 elems per row (bank-conflict-free)

__global__ __launch_bounds__(256, 2)
void gemm_mma_kernel(const float* __restrict__ A,
                     const uint32_t* __restrict__ Bh,
                     const uint32_t* __restrict__ Bl,
                     const float* __restrict__ bias,
                     float* __restrict__ C, int M)
{
    extern __shared__ __nv_bfloat16 sA[];     // [2][64][A_STRIDE]
    __nv_bfloat16* Ah = sA;
    __nv_bfloat16* Al = sA + 64 * A_STRIDE;

    const int tid = threadIdx.x;
    const int m0  = blockIdx.x * 64;

#pragma unroll
    for (int it = 0; it < 16; it++) {
        int p  = tid + it * 256;
        int m  = p >> 6;
        int kp = (p & 63) << 1;
        float2 v = make_float2(0.f, 0.f);
        if (m0 + m < M)
            v = *reinterpret_cast<const float2*>(&A[(size_t)(m0 + m) * 128 + kp]);
        uint32_t hp, lp;
        split_pair(v.x, v.y, hp, lp);
        *reinterpret_cast<uint32_t*>(&Ah[m * A_STRIDE + kp]) = hp;
        *reinterpret_cast<uint32_t*>(&Al[m * A_STRIDE + kp]) = lp;
    }
    __syncthreads();

    const int wid  = tid >> 5;
    const int lane = tid & 31;
    const int wm   = wid & 1;
    const int wn   = wid >> 1;
    const int g    = lane >> 2;
    const int tg   = lane & 3;

    float acc[2][4][4];
#pragma unroll
    for (int mf = 0; mf < 2; mf++)
#pragma unroll
        for (int t4 = 0; t4 < 4; t4++)
#pragma unroll
            for (int i = 0; i < 4; i++) acc[mf][t4][i] = 0.f;

#pragma unroll
    for (int k = 0; k < 8; k++) {
        uint32_t ah[2][4], al[2][4];
        const int cb = k * 16 + tg * 2;
#pragma unroll
        for (int mf = 0; mf < 2; mf++) {
            int r = wm * 32 + mf * 16 + g;
            ah[mf][0] = *reinterpret_cast<const uint32_t*>(&Ah[r * A_STRIDE + cb]);
            ah[mf][1] = *reinterpret_cast<const uint32_t*>(&Ah[(r + 8) * A_STRIDE + cb]);
            ah[mf][2] = *reinterpret_cast<const uint32_t*>(&Ah[r * A_STRIDE + cb + 8]);
            ah[mf][3] = *reinterpret_cast<const uint32_t*>(&Ah[(r + 8) * A_STRIDE + cb + 8]);
            al[mf][0] = *reinterpret_cast<const uint32_t*>(&Al[r * A_STRIDE + cb]);
            al[mf][1] = *reinterpret_cast<const uint32_t*>(&Al[(r + 8) * A_STRIDE + cb]);
            al[mf][2] = *reinterpret_cast<const uint32_t*>(&Al[r * A_STRIDE + cb + 8]);
            al[mf][3] = *reinterpret_cast<const uint32_t*>(&Al[(r + 8) * A_STRIDE + cb + 8]);
        }
#pragma unroll
        for (int t4 = 0; t4 < 4; t4++) {
            int fidx = (((wn * 4 + t4) * 8 + k) * 32 + lane) * 2;
            uint32_t bh0 = __ldg(&Bh[fidx]);
            uint32_t bh1 = __ldg(&Bh[fidx + 1]);
            uint32_t bl0 = __ldg(&Bl[fidx]);
            uint32_t bl1 = __ldg(&Bl[fidx + 1]);
#pragma unroll
            for (int mf = 0; mf < 2; mf++) {
                mma16816(acc[mf][t4], ah[mf], bh0, bh1);
                mma16816(acc[mf][t4], ah[mf], bl0, bl1);
                mma16816(acc[mf][t4], al[mf], bh0, bh1);
            }
        }
    }

#pragma unroll
    for (int t4 = 0; t4 < 4; t4++) {
        int col = wn * 32 + t4 * 8 + tg * 2;
        float b0 = bias ? __ldg(&bias[col])     : 0.f;
        float b1 = bias ? __ldg(&bias[col + 1]) : 0.f;
#pragma unroll
        for (int mf = 0; mf < 2; mf++) {
            int row = m0 + wm * 32 + mf * 16 + g;
            if (row < M) {
                float2 o0 = make_float2(acc[mf][t4][0] + b0, acc[mf][t4][1] + b1);
                *reinterpret_cast<float2*>(&C[(size_t)row * 128 + col]) = o0;
            }
            if (row + 8 < M) {
                float2 o1 = make_float2(acc[mf][t4][2] + b0, acc[mf][t4][3] + b1);
                *reinterpret_cast<float2*>(&C[(size_t)(row + 8) * 128 + col]) = o1;
            }
        }
    }
}

// ---------------------------------------------------------------------------
// CSR offsets from sorted seg_i
// ---------------------------------------------------------------------------
__global__ void offsets_kernel(const int* __restrict__ seg_i, int num_edges, int num_atoms)
{
    int a = blockIdx.x * blockDim.x + threadIdx.x;
    if (a > num_atoms) return;
    int lo = 0, hi = num_edges;
    while (lo < hi) {
        int mid = (lo + hi) >> 1;
        if (seg_i[mid] < a) lo = mid + 1; else hi = mid;
    }
    g_rowstart[a] = lo;
}

// ---------------------------------------------------------------------------
// Edge kernel: one warp per atom, grid-stride over atoms for load balance.
// Lane owns 4 channels. Index prefetch breaks the idx->gather chain;
// w_ij streamed with evict-first so the f table stays L2-resident.
// ---------------------------------------------------------------------------
#define CONV_BLOCKS 1184

__global__ __launch_bounds__(256)
void conv_kernel(const float* __restrict__ w_ij, const int* __restrict__ idx_j,
                 int num_atoms)
{
    const int warp   = threadIdx.x >> 5;
    const int lane   = threadIdx.x & 31;
    const int nwarps = gridDim.x * 8;
    const int wg     = blockIdx.x * 8 + warp;
    const int c      = lane * 4;

    for (int a = wg; a < num_atoms; a += nwarps) {
        const int s = g_rowstart[a];
        const int e = g_rowstart[a + 1];

        float4 acc = make_float4(0.f, 0.f, 0.f, 0.f);

        int k = s;
        int j0 = 0, j1 = 0, j2 = 0, j3 = 0;
        if (k + 3 < e) {
            j0 = __ldg(&idx_j[k]);     j1 = __ldg(&idx_j[k + 1]);
            j2 = __ldg(&idx_j[k + 2]); j3 = __ldg(&idx_j[k + 3]);
        }
        while (k + 3 < e) {
            // prefetch next group's indices before this group's FMAs
            int t0 = 0, t1 = 0, t2 = 0, t3 = 0;
            if (k + 7 < e) {
                t0 = __ldg(&idx_j[k + 4]); t1 = __ldg(&idx_j[k + 5]);
                t2 = __ldg(&idx_j[k + 6]); t3 = __ldg(&idx_j[k + 7]);
            }
            float4 w0 = __ldcs(reinterpret_cast<const float4*>(&w_ij[(size_t)k * 128 + c]));
            float4 w1 = __ldcs(reinterpret_cast<const float4*>(&w_ij[(size_t)(k + 1) * 128 + c]));
            float4 w2 = __ldcs(reinterpret_cast<const float4*>(&w_ij[(size_t)(k + 2) * 128 + c]));
            float4 w3 = __ldcs(reinterpret_cast<const float4*>(&w_ij[(size_t)(k + 3) * 128 + c]));
            float4 f0 = __ldg(reinterpret_cast<const float4*>(&g_f[(size_t)j0 * 128 + c]));
            float4 f1 = __ldg(reinterpret_cast<const float4*>(&g_f[(size_t)j1 * 128 + c]));
            float4 f2 = __ldg(reinterpret_cast<const float4*>(&g_f[(size_t)j2 * 128 + c]));
            float4 f3 = __ldg(reinterpret_cast<const float4*>(&g_f[(size_t)j3 * 128 + c]));
            acc.x = fmaf(w0.x, f0.x, acc.x); acc.y = fmaf(w0.y, f0.y, acc.y);
            acc.z = fmaf(w0.z, f0.z, acc.z); acc.w = fmaf(w0.w, f0.w, acc.w);
            acc.x = fmaf(w1.x, f1.x, acc.x); acc.y = fmaf(w1.y, f1.y, acc.y);
            acc.z = fmaf(w1.z, f1.z, acc.z); acc.w = fmaf(w1.w, f1.w, acc.w);
            acc.x = fmaf(w2.x, f2.x, acc.x); acc.y = fmaf(w2.y, f2.y, acc.y);
            acc.z = fmaf(w2.z, f2.z, acc.z); acc.w = fmaf(w2.w, f2.w, acc.w);
            acc.x = fmaf(w3.x, f3.x, acc.x); acc.y = fmaf(w3.y, f3.y, acc.y);
            acc.z = fmaf(w3.z, f3.z, acc.z); acc.w = fmaf(w3.w, f3.w, acc.w);
            j0 = t0; j1 = t1; j2 = t2; j3 = t3;
            k += 4;
        }
        for (; k < e; k++) {
            int j = __ldg(&idx_j[k]);
            float4 w0 = __ldcs(reinterpret_cast<const float4*>(&w_ij[(size_t)k * 128 + c]));
            float4 f0 = __ldg(reinterpret_cast<const float4*>(&g_f[(size_t)j * 128 + c]));
            acc.x = fmaf(w0.x, f0.x, acc.x); acc.y = fmaf(w0.y, f0.y, acc.y);
            acc.z = fmaf(w0.z, f0.z, acc.z); acc.w = fmaf(w0.w, f0.w, acc.w);
        }

        *reinterpret_cast<float4*>(&g_conv[(size_t)a * 128 + c]) = acc;
    }
}

// ---------------------------------------------------------------------------
extern "C" void kernel_launch(void* const* d_in, const int* in_sizes, int n_in,
                              void* d_out, int out_size)
{
    const float* x    = (const float*)d_in[0];
    const float* wij  = (const float*)d_in[1];
    const int*   seg  = (const int*)d_in[2];
    const int*   idxj = (const int*)d_in[3];
    int base = 4;
    if (n_in >= 8 && in_sizes[4] == 1) base = 5;   // skip scalar seg_i_sum
    const float* Win  = (const float*)d_in[base];
    const float* Wout = (const float*)d_in[base + 1];
    const float* bout = (const float*)d_in[base + 2];

    int num_edges = in_sizes[2];
    int num_atoms = out_size / NFM;
    if (num_atoms > MAX_ATOMS) num_atoms = MAX_ATOMS;
    if (num_edges > MAX_EDGES) num_edges = MAX_EDGES;

    float*    f_ptr    = nullptr;
    float*    conv_ptr = nullptr;
    uint32_t* bfrag    = nullptr;
    cudaGetSymbolAddress((void**)&f_ptr, g_f);
    cudaGetSymbolAddress((void**)&conv_ptr, g_conv);
    cudaGetSymbolAddress((void**)&bfrag, g_Bfrag);

    const int SMEM_A = 2 * 64 * A_STRIDE * (int)sizeof(__nv_bfloat16);  // 34816
    cudaFuncSetAttribute(gemm_mma_kernel,
                         cudaFuncAttributeMaxDynamicSharedMemorySize, SMEM_A);

    int gblocks = (num_atoms + 63) / 64;

    // 0) pack weights into mma B fragments (hi/lo)
    prep_weights_kernel<<<128, 256>>>(Win, Wout);

    // 1) CSR offsets
    offsets_kernel<<<(num_atoms + 1 + 255) / 256, 256>>>(seg, num_edges, num_atoms);

    // 2) f = x @ W_in
    gemm_mma_kernel<<<gblocks, 256, SMEM_A>>>(
        x, bfrag + 0 * 8192, bfrag + 1 * 8192, nullptr, f_ptr, num_atoms);

    // 3) conv = segment_sum(w_ij * f[idx_j])
    conv_kernel<<<CONV_BLOCKS, 256>>>(wij, idxj, num_atoms);

    // 4) out = conv @ W_out + b_out
    gemm_mma_kernel<<<gblocks, 256, SMEM_A>>>(
        conv_ptr, bfrag + 2 * 8192, bfrag + 3 * 8192, bout, (float*)d_out, num_atoms);
}